// round 1
// baseline (speedup 1.0000x reference)
#include <cuda_runtime.h>
#include <mma.h>
#include <cstdint>

using namespace nvcuda;

// Problem constants
#define BB   64
#define TT   200
#define INF  512
#define HID  1024
#define OUTF 512
#define DELAYS 20
#define BH   (BB * HID)          // 65536
#define NBLK (TT / DELAYS)       // 10

// ---------------- scratch (device globals; no allocation allowed) ----------
__device__ float g_xproj[(size_t)TT * BH];        // [T][B][H] input projection
__device__ float g_firing[(size_t)TT * BH];       // [T][B][H] firing rates
__device__ float g_latproj[(size_t)DELAYS * BH];  // [20][B][H] lateral proj for one block
__device__ float g_tmpout[(size_t)TT * BB * OUTF];// [T*B][OUT] pre-permute output
__device__ float g_volt[BH];
__device__ float g_asc[2 * BH];
__device__ float g_fire[BH];

// ---------------- tf32 GEMM: C[M,N] = A[M,K] @ B[K,N] ----------------------
// AMODE: 0 = A rows contiguous with stride lda
//        1 = A row m maps to x[b][t][:] with m = t*64 + b   (input projection)
// BTRANS: 0 = B is [K,N] row-major (ldb = N stride)
//         1 = B is [N,K] row-major (W_out), transposed while staging to smem
static constexpr int BMT = 128;
static constexpr int BKT = 32;

template<int BN, int AMODE, int BTRANS>
__global__ __launch_bounds__(256) void gemm_tf32(
    const float* __restrict__ A, const float* __restrict__ Bm,
    float* __restrict__ C, int M, int N, int K, int lda, int ldb)
{
    __shared__ float As[BMT][BKT + 4];
    __shared__ float Bs[BKT][BN + 4];

    const int tid  = threadIdx.x;
    const int warp = tid >> 5;
    const int bm   = blockIdx.y * BMT;
    const int bn   = blockIdx.x * BN;
    // 8 warps: 4 along M (32 rows each), 2 along N (BN/2 cols each)
    const int wm = (warp >> 1) * 32;
    const int wn = (warp & 1) * (BN / 2);
    constexpr int NF = BN / 32;  // 16-wide fragments per warp in N

    wmma::fragment<wmma::accumulator, 16, 16, 8, float> acc[2][NF];
#pragma unroll
    for (int i = 0; i < 2; i++)
#pragma unroll
        for (int j = 0; j < NF; j++)
            wmma::fill_fragment(acc[i][j], 0.0f);

    for (int k0 = 0; k0 < K; k0 += BKT) {
        // ---- stage A tile (128 x 32) : 256 threads x 4 float4 ----
#pragma unroll
        for (int i = 0; i < 4; i++) {
            int m  = (tid >> 3) + i * 32;
            int kk = (tid & 7) * 4;
            int gm = bm + m;
            const float* arow;
            if (AMODE == 0) {
                arow = A + (size_t)gm * lda;
            } else {
                int b = gm & (BB - 1);
                int t = gm >> 6;
                arow = A + ((size_t)b * TT + t) * lda;
            }
            float4 v = *reinterpret_cast<const float4*>(arow + k0 + kk);
            *reinterpret_cast<float4*>(&As[m][kk]) = v;
        }
        // ---- stage B tile (32 x BN) ----
        if (BTRANS == 0) {
            constexpr int NV  = BN / 4;     // float4 per smem row
            constexpr int RPI = 256 / NV;   // rows per iteration
#pragma unroll
            for (int i = 0; i < BKT / RPI; i++) {
                int kk = (tid / NV) + i * RPI;
                int nn = (tid % NV) * 4;
                float4 v = *reinterpret_cast<const float4*>(
                    Bm + (size_t)(k0 + kk) * ldb + bn + nn);
                *reinterpret_cast<float4*>(&Bs[kk][nn]) = v;
            }
        } else {
            // B is [N][K]; read coalesced along K, transpose into Bs[k][n]
#pragma unroll
            for (int i = 0; i < BN / 32; i++) {
                int n  = (tid >> 3) + i * 32;
                int kk = (tid & 7) * 4;
                float4 v = *reinterpret_cast<const float4*>(
                    Bm + (size_t)(bn + n) * ldb + k0 + kk);
                Bs[kk + 0][n] = v.x;
                Bs[kk + 1][n] = v.y;
                Bs[kk + 2][n] = v.z;
                Bs[kk + 3][n] = v.w;
            }
        }
        __syncthreads();

        // ---- compute: 4 k-steps of 8 ----
#pragma unroll
        for (int ks = 0; ks < BKT; ks += 8) {
            wmma::fragment<wmma::matrix_a, 16, 16, 8, wmma::precision::tf32, wmma::row_major> af[2];
            wmma::fragment<wmma::matrix_b, 16, 16, 8, wmma::precision::tf32, wmma::row_major> bf[NF];
#pragma unroll
            for (int i = 0; i < 2; i++) {
                wmma::load_matrix_sync(af[i], &As[wm + i * 16][ks], BKT + 4);
#pragma unroll
                for (int e = 0; e < af[i].num_elements; e++)
                    af[i].x[e] = wmma::__float_to_tf32(af[i].x[e]);
            }
#pragma unroll
            for (int j = 0; j < NF; j++) {
                wmma::load_matrix_sync(bf[j], &Bs[ks][wn + j * 16], BN + 4);
#pragma unroll
                for (int e = 0; e < bf[j].num_elements; e++)
                    bf[j].x[e] = wmma::__float_to_tf32(bf[j].x[e]);
            }
#pragma unroll
            for (int i = 0; i < 2; i++)
#pragma unroll
                for (int j = 0; j < NF; j++)
                    wmma::mma_sync(acc[i][j], af[i], bf[j], acc[i][j]);
        }
        __syncthreads();
    }

#pragma unroll
    for (int i = 0; i < 2; i++)
#pragma unroll
        for (int j = 0; j < NF; j++)
            wmma::store_matrix_sync(
                C + (size_t)(bm + wm + i * 16) * N + bn + wn + j * 16,
                acc[i][j], N, wmma::mem_row_major);
}

// ---------------- elementwise 20-step scan ---------------------------------
__device__ __forceinline__ float sigm(float x) { return 1.0f / (1.0f + __expf(-x)); }

__global__ __launch_bounds__(256) void scan_kernel(
    const float* __restrict__ xproj,    // [T][B*H]
    const float* __restrict__ latproj,  // [20][B*H] or nullptr (block 0)
    const float* __restrict__ trans_k_m,
    const float* __restrict__ trans_asc_k,
    const float* __restrict__ asc_amp,
    const float* __restrict__ trans_asc_r,
    const float* __restrict__ thresh,
    float* __restrict__ firing,         // [T][B*H]
    float* __restrict__ volt_st, float* __restrict__ asc_st,
    float* __restrict__ fire_st, int t0)
{
    int idx = blockIdx.x * blockDim.x + threadIdx.x;  // over B*H
    int h = idx & (HID - 1);

    float km  = sigm(trans_k_m[h]);               // DT*k_m in (0,1)
    float c1  = 0.1f * km;                        // R_MEM * DT * k_m
    float c2  = 1.0f - km;
    float ka0 = sigm(trans_asc_k[h]);
    float ka1 = sigm(trans_asc_k[HID + h]);
    float amp0 = asc_amp[h],       amp1 = asc_amp[HID + h];
    float r0 = 1.0f - 2.0f * sigm(trans_asc_r[h]);
    float r1 = 1.0f - 2.0f * sigm(trans_asc_r[HID + h]);
    float th = thresh[h];

    float f, v, a0, a1;
    if (t0 == 0) {
        f = 0.f; v = 0.f; a0 = 0.f; a1 = 0.f;
    } else {
        f  = fire_st[idx];
        v  = volt_st[idx];
        a0 = asc_st[idx];
        a1 = asc_st[BH + idx];
    }

#pragma unroll
    for (int s = 0; s < DELAYS; s++) {
        float syn = xproj[(size_t)(t0 + s) * BH + idx];
        if (latproj) syn += latproj[(size_t)s * BH + idx];
        a0 = (amp0 + r0 * a0) * f * ka0 + (1.0f - ka0) * a0;
        a1 = (amp1 + r1 * a1) * f * ka1 + (1.0f - ka1) * a1;
        v  = c1 * (syn + a0 + a1) + c2 * v;
        f  = sigm(v - th);
        firing[(size_t)(t0 + s) * BH + idx] = f;
    }
    fire_st[idx] = f;
    volt_st[idx] = v;
    asc_st[idx] = a0;
    asc_st[BH + idx] = a1;
}

// ---------------- output permute + bias ------------------------------------
__global__ __launch_bounds__(256) void epilogue_kernel(
    const float* __restrict__ tmp, const float* __restrict__ bias,
    float* __restrict__ out)
{
    int q  = blockIdx.x * blockDim.x + threadIdx.x;  // float4 index
    int o4 = q % (OUTF / 4);
    int m  = q / (OUTF / 4);
    int t = m / BB;
    int b = m % BB;
    float4 v  = reinterpret_cast<const float4*>(tmp)[q];
    float4 bb = reinterpret_cast<const float4*>(bias)[o4];
    v.x += bb.x; v.y += bb.y; v.z += bb.z; v.w += bb.w;
    reinterpret_cast<float4*>(out)[((size_t)b * TT + t) * (OUTF / 4) + o4] = v;
}

// ---------------- launch ----------------------------------------------------
extern "C" void kernel_launch(void* const* d_in, const int* in_sizes, int n_in,
                              void* d_out, int out_size)
{
    const float* x           = (const float*)d_in[0];
    const float* W_in        = (const float*)d_in[1];
    const float* W_lat       = (const float*)d_in[2];
    const float* thresh      = (const float*)d_in[3];
    const float* trans_k_m   = (const float*)d_in[4];
    const float* trans_asc_k = (const float*)d_in[5];
    const float* asc_amp     = (const float*)d_in[6];
    const float* trans_asc_r = (const float*)d_in[7];
    const float* W_out       = (const float*)d_in[8];
    const float* b_out       = (const float*)d_in[9];
    float* out = (float*)d_out;

    float *xproj, *firing, *latproj, *tmpout, *volt, *asc, *fire;
    cudaGetSymbolAddress((void**)&xproj,   g_xproj);
    cudaGetSymbolAddress((void**)&firing,  g_firing);
    cudaGetSymbolAddress((void**)&latproj, g_latproj);
    cudaGetSymbolAddress((void**)&tmpout,  g_tmpout);
    cudaGetSymbolAddress((void**)&volt,    g_volt);
    cudaGetSymbolAddress((void**)&asc,     g_asc);
    cudaGetSymbolAddress((void**)&fire,    g_fire);

    // 1. input projection: xproj[t*64+b][h] = x[b][t][:] @ W_in
    gemm_tf32<128, 1, 0><<<dim3(HID / 128, (BB * TT) / 128), 256>>>(
        x, W_in, xproj, BB * TT, HID, INF, INF, HID);

    // 2. ten blocks of 20 steps: batched lateral GEMM + elementwise scan
    for (int blk = 0; blk < NBLK; blk++) {
        const float* lp = nullptr;
        if (blk > 0) {
            gemm_tf32<64, 0, 0><<<dim3(HID / 64, (DELAYS * BB) / 128), 256>>>(
                firing + (size_t)(blk - 1) * DELAYS * BH, W_lat, latproj,
                DELAYS * BB, HID, HID, HID, HID);
            lp = latproj;
        }
        scan_kernel<<<BH / 256, 256>>>(
            xproj, lp, trans_k_m, trans_asc_k, asc_amp, trans_asc_r, thresh,
            firing, volt, asc, fire, blk * DELAYS);
    }

    // 3. readout: tmp[m][o] = firing[m][:] @ W_out[o][:]
    gemm_tf32<128, 0, 1><<<dim3(OUTF / 128, (BB * TT) / 128), 256>>>(
        firing, W_out, tmpout, BB * TT, OUTF, HID, HID, HID);

    // 4. permute to [B][T][OUT] and add bias
    epilogue_kernel<<<((size_t)TT * BB * OUTF / 4) / 256, 256>>>(tmpout, b_out, out);
}

// round 2
// speedup vs baseline: 3.3314x; 3.3314x over previous
#include <cuda_runtime.h>
#include <cuda_fp16.h>
#include <mma.h>
#include <cstdint>

using namespace nvcuda;

#define BB   64
#define TT   200
#define INF  512
#define HID  1024
#define OUTF 512
#define DELAYS 20
#define BH   (BB * HID)          // 65536
#define NBLK (TT / DELAYS)       // 10

// ---------------- scratch (device globals) ----------------------------------
__device__ __half g_xh[(size_t)TT * BB * INF];    // permuted fp16 input [t*64+b][IN]
__device__ __half g_Win[(size_t)INF * HID];
__device__ __half g_Wlat[(size_t)HID * HID];
__device__ __half g_WoutT[(size_t)HID * OUTF];    // [H][O]
__device__ float  g_brep[16 * OUTF];              // bias replicated 16 rows
__device__ float  g_syn[(size_t)TT * BH];         // xproj, then +=latproj per block
__device__ __half g_firing[(size_t)TT * BH];      // [T][B*H] fp16
__device__ float  g_volt[BH];
__device__ float  g_asc[2 * BH];
__device__ float  g_fire[BH];

// ---------------- cp.async helpers ------------------------------------------
__device__ __forceinline__ void cp16(void* dst, const void* src) {
    uint32_t d = (uint32_t)__cvta_generic_to_shared(dst);
    asm volatile("cp.async.cg.shared.global [%0], [%1], 16;\n" :: "r"(d), "l"(src));
}
__device__ __forceinline__ void cp_commit() { asm volatile("cp.async.commit_group;\n"); }
__device__ __forceinline__ void cp_wait1()  { asm volatile("cp.async.wait_group 1;\n"); }

// ---------------- fp16 GEMM: C[M,N] = A[M,K] @ B[K,N], fp32 accum -----------
// MODE 0: plain store      MODE 1: C += acc (in-place accumulate)
// MODE 2: permuted store to out[(b*TT+t)*OUTF + n] with bias from g_brep
static constexpr int BM = 128;
static constexpr int BK = 32;

template<int BN, int MODE>
__global__ __launch_bounds__(256) void hgemm(
    const __half* __restrict__ A, const __half* __restrict__ Bm,
    float* __restrict__ C, int M, int N, int K)
{
    __shared__ alignas(16) __half As[2][BM][BK + 8];
    __shared__ alignas(16) __half Bs[2][BK][BN + 8];

    const int tid  = threadIdx.x;
    const int warp = tid >> 5;
    const int bm   = blockIdx.y * BM;
    const int bn   = blockIdx.x * BN;
    const int wm   = (warp >> 1) * 32;
    const int wn   = (warp & 1) * (BN / 2);
    constexpr int NF = BN / 32;

    wmma::fragment<wmma::accumulator, 16, 16, 16, float> acc[2][NF];
#pragma unroll
    for (int i = 0; i < 2; i++)
#pragma unroll
        for (int j = 0; j < NF; j++)
            wmma::fill_fragment(acc[i][j], 0.0f);

    const int KT = K / BK;

    auto load_tiles = [&](int kt, int st) {
        int k0 = kt * BK;
        // A tile: 128x32 halves = 512 x 16B chunks, 2 per thread
#pragma unroll
        for (int i = 0; i < 2; i++) {
            int c   = tid * 2 + i;
            int row = c >> 2;
            int col = (c & 3) * 8;
            cp16(&As[st][row][col], A + (size_t)(bm + row) * K + k0 + col);
        }
        // B tile: 32xBN halves
        if (BN == 128) {
#pragma unroll
            for (int i = 0; i < 2; i++) {
                int c   = tid * 2 + i;
                int row = c >> 4;
                int col = (c & 15) * 8;
                cp16(&Bs[st][row][col], Bm + (size_t)(k0 + row) * N + bn + col);
            }
        } else { // BN == 64: 256 chunks, 1 per thread
            int row = tid >> 3;
            int col = (tid & 7) * 8;
            cp16(&Bs[st][row][col], Bm + (size_t)(k0 + row) * N + bn + col);
        }
    };

    load_tiles(0, 0);
    cp_commit();

    for (int kt = 0; kt < KT; kt++) {
        int st = kt & 1;
        if (kt + 1 < KT) load_tiles(kt + 1, st ^ 1);
        cp_commit();
        cp_wait1();
        __syncthreads();

#pragma unroll
        for (int ks = 0; ks < BK; ks += 16) {
            wmma::fragment<wmma::matrix_a, 16, 16, 16, __half, wmma::row_major> af[2];
            wmma::fragment<wmma::matrix_b, 16, 16, 16, __half, wmma::row_major> bf[NF];
#pragma unroll
            for (int i = 0; i < 2; i++)
                wmma::load_matrix_sync(af[i], &As[st][wm + i * 16][ks], BK + 8);
#pragma unroll
            for (int j = 0; j < NF; j++)
                wmma::load_matrix_sync(bf[j], &Bs[st][ks][wn + j * 16], BN + 8);
#pragma unroll
            for (int i = 0; i < 2; i++)
#pragma unroll
                for (int j = 0; j < NF; j++)
                    wmma::mma_sync(acc[i][j], af[i], bf[j], acc[i][j]);
        }
        __syncthreads();
    }

    // ---- epilogue ----
#pragma unroll
    for (int i = 0; i < 2; i++) {
#pragma unroll
        for (int j = 0; j < NF; j++) {
            int mbase = bm + wm + i * 16;
            int nbase = bn + wn + j * 16;
            if (MODE == 0) {
                wmma::store_matrix_sync(C + (size_t)mbase * N + nbase,
                                        acc[i][j], N, wmma::mem_row_major);
            } else if (MODE == 1) {
                float* p = C + (size_t)mbase * N + nbase;
                wmma::fragment<wmma::accumulator, 16, 16, 16, float> cf;
                wmma::load_matrix_sync(cf, p, N, wmma::mem_row_major);
#pragma unroll
                for (int e = 0; e < cf.num_elements; e++)
                    acc[i][j].x[e] += cf.x[e];
                wmma::store_matrix_sync(p, acc[i][j], N, wmma::mem_row_major);
            } else { // MODE 2: bias + permuted store
                wmma::fragment<wmma::accumulator, 16, 16, 16, float> cf;
                wmma::load_matrix_sync(cf, g_brep + nbase, OUTF, wmma::mem_row_major);
#pragma unroll
                for (int e = 0; e < cf.num_elements; e++)
                    acc[i][j].x[e] += cf.x[e];
                int t  = mbase >> 6;          // fixed within 16-row fragment
                int b0 = mbase & 63;
                float* p = C + ((size_t)b0 * TT + t) * OUTF + nbase;
                wmma::store_matrix_sync(p, acc[i][j], (unsigned)(TT * OUTF),
                                        wmma::mem_row_major);
            }
        }
    }
}

// ---------------- conversion kernels -----------------------------------------
__global__ __launch_bounds__(256) void convx_kernel(const float* __restrict__ x,
                                                    __half* __restrict__ xh)
{
    int i  = blockIdx.x * 256 + threadIdx.x;          // over B*T*IN/4
    int i4 = i % (INF / 4);
    int bt = i / (INF / 4);
    int b = bt / TT, t = bt % TT;
    float4 v = reinterpret_cast<const float4*>(x)[i];
    int dst = (t * BB + b) * (INF / 4) + i4;
    reinterpret_cast<__half2*>(xh)[2 * dst + 0] = __floats2half2_rn(v.x, v.y);
    reinterpret_cast<__half2*>(xh)[2 * dst + 1] = __floats2half2_rn(v.z, v.w);
}

__global__ __launch_bounds__(256) void f2h_kernel(const float* __restrict__ in,
                                                  __half* __restrict__ out)
{
    int i = blockIdx.x * 256 + threadIdx.x;
    float4 v = reinterpret_cast<const float4*>(in)[i];
    reinterpret_cast<__half2*>(out)[2 * i + 0] = __floats2half2_rn(v.x, v.y);
    reinterpret_cast<__half2*>(out)[2 * i + 1] = __floats2half2_rn(v.z, v.w);
}

// W_out [OUT][HID] fp32 -> WoutT [HID][OUT] fp16
__global__ void transp_kernel(const float* __restrict__ w, __half* __restrict__ wt)
{
    __shared__ float tile[32][33];
    int ox = blockIdx.x * 32, hy = blockIdx.y * 32;
    int tx = threadIdx.x, ty = threadIdx.y;   // 32 x 8
#pragma unroll
    for (int r = 0; r < 32; r += 8)
        tile[ty + r][tx] = w[(size_t)(ox + ty + r) * HID + hy + tx];
    __syncthreads();
#pragma unroll
    for (int r = 0; r < 32; r += 8)
        wt[(size_t)(hy + ty + r) * OUTF + ox + tx] = __float2half(tile[tx][ty + r]);
}

__global__ void brep_kernel(const float* __restrict__ b)
{
    int i = blockIdx.x * 256 + threadIdx.x;   // 16*OUTF
    g_brep[i] = b[i % OUTF];
}

// ---------------- elementwise 20-step scan -----------------------------------
__device__ __forceinline__ float sigm(float x) { return 1.0f / (1.0f + __expf(-x)); }

__global__ __launch_bounds__(256) void scan_kernel(
    const float* __restrict__ syn_all,       // [T][B*H] (input-proj + lateral)
    const float* __restrict__ trans_k_m,
    const float* __restrict__ trans_asc_k,
    const float* __restrict__ asc_amp,
    const float* __restrict__ trans_asc_r,
    const float* __restrict__ thresh,
    __half* __restrict__ firing,
    float* __restrict__ volt_st, float* __restrict__ asc_st,
    float* __restrict__ fire_st, int t0)
{
    int idx = blockIdx.x * blockDim.x + threadIdx.x;
    int h = idx & (HID - 1);

    // prefetch all synaptic inputs (MLP = 20)
    float syn[DELAYS];
#pragma unroll
    for (int s = 0; s < DELAYS; s++)
        syn[s] = syn_all[(size_t)(t0 + s) * BH + idx];

    float km  = sigm(trans_k_m[h]);
    float c1  = 0.1f * km;
    float c2  = 1.0f - km;
    float ka0 = sigm(trans_asc_k[h]);
    float ka1 = sigm(trans_asc_k[HID + h]);
    float amp0 = asc_amp[h],       amp1 = asc_amp[HID + h];
    float r0 = 1.0f - 2.0f * sigm(trans_asc_r[h]);
    float r1 = 1.0f - 2.0f * sigm(trans_asc_r[HID + h]);
    float th = thresh[h];

    float f, v, a0, a1;
    if (t0 == 0) {
        f = 0.f; v = 0.f; a0 = 0.f; a1 = 0.f;
    } else {
        f  = fire_st[idx];
        v  = volt_st[idx];
        a0 = asc_st[idx];
        a1 = asc_st[BH + idx];
    }

#pragma unroll
    for (int s = 0; s < DELAYS; s++) {
        a0 = (amp0 + r0 * a0) * f * ka0 + (1.0f - ka0) * a0;
        a1 = (amp1 + r1 * a1) * f * ka1 + (1.0f - ka1) * a1;
        v  = c1 * (syn[s] + a0 + a1) + c2 * v;
        f  = sigm(v - th);
        firing[(size_t)(t0 + s) * BH + idx] = __float2half(f);
    }
    fire_st[idx] = f;
    volt_st[idx] = v;
    asc_st[idx] = a0;
    asc_st[BH + idx] = a1;
}

// ---------------- launch ------------------------------------------------------
extern "C" void kernel_launch(void* const* d_in, const int* in_sizes, int n_in,
                              void* d_out, int out_size)
{
    const float* x           = (const float*)d_in[0];
    const float* W_in        = (const float*)d_in[1];
    const float* W_lat       = (const float*)d_in[2];
    const float* thresh      = (const float*)d_in[3];
    const float* trans_k_m   = (const float*)d_in[4];
    const float* trans_asc_k = (const float*)d_in[5];
    const float* asc_amp     = (const float*)d_in[6];
    const float* trans_asc_r = (const float*)d_in[7];
    const float* W_out       = (const float*)d_in[8];
    const float* b_out       = (const float*)d_in[9];
    float* out = (float*)d_out;

    __half *xh, *Win, *Wlat, *WoutT, *firing;
    float *syn, *volt, *asc, *fire;
    cudaGetSymbolAddress((void**)&xh,     g_xh);
    cudaGetSymbolAddress((void**)&Win,    g_Win);
    cudaGetSymbolAddress((void**)&Wlat,   g_Wlat);
    cudaGetSymbolAddress((void**)&WoutT,  g_WoutT);
    cudaGetSymbolAddress((void**)&syn,    g_syn);
    cudaGetSymbolAddress((void**)&firing, g_firing);
    cudaGetSymbolAddress((void**)&volt,   g_volt);
    cudaGetSymbolAddress((void**)&asc,    g_asc);
    cudaGetSymbolAddress((void**)&fire,   g_fire);

    // 0. conversions
    convx_kernel<<<(BB * TT * INF / 4) / 256, 256>>>(x, xh);
    f2h_kernel<<<(INF * HID / 4) / 256, 256>>>(W_in, Win);
    f2h_kernel<<<(HID * HID / 4) / 256, 256>>>(W_lat, Wlat);
    transp_kernel<<<dim3(OUTF / 32, HID / 32), dim3(32, 8)>>>(W_out, WoutT);
    brep_kernel<<<(16 * OUTF) / 256, 256>>>(b_out);

    // 1. input projection: syn[t*64+b][h] = xh @ Win
    hgemm<128, 0><<<dim3(HID / 128, (BB * TT) / BM), 256>>>(
        xh, Win, syn, BB * TT, HID, INF);

    // 2. ten blocks: lateral GEMM accumulates into syn slice, then scan
    for (int blk = 0; blk < NBLK; blk++) {
        if (blk > 0) {
            hgemm<64, 1><<<dim3(HID / 64, (DELAYS * BB) / BM), 256>>>(
                firing + (size_t)(blk - 1) * DELAYS * BH, Wlat,
                syn + (size_t)blk * DELAYS * BH,
                DELAYS * BB, HID, HID);
        }
        scan_kernel<<<BH / 256, 256>>>(
            syn, trans_k_m, trans_asc_k, asc_amp, trans_asc_r, thresh,
            firing, volt, asc, fire, blk * DELAYS);
    }

    // 3. readout: out[(b*TT+t)][o] = firing @ WoutT + bias (fused permute+bias)
    hgemm<128, 2><<<dim3(OUTF / 128, (BB * TT) / BM), 256>>>(
        firing, WoutT, out, BB * TT, OUTF, HID);
}

// round 3
// speedup vs baseline: 4.8040x; 1.4420x over previous
#include <cuda_runtime.h>
#include <cuda_fp16.h>
#include <cstdint>

#define BB   64
#define TT   200
#define INF  512
#define HID  1024
#define OUTF 512
#define DELAYS 20
#define BH   (BB * HID)          // 65536
#define NBLK (TT / DELAYS)       // 10
#define STG  3

// ---------------- scratch (device globals) ----------------------------------
__device__ __half g_xh[(size_t)TT * BB * INF];    // permuted fp16 input [t*64+b][IN]
__device__ __half g_Win[(size_t)INF * HID];
__device__ __half g_Wlat[(size_t)HID * HID];
__device__ __half g_WoutT[(size_t)HID * OUTF];    // [H][O]
__device__ float  g_syn[(size_t)TT * BH];         // xproj then += lateral
__device__ __half g_firing[(size_t)TT * BH];      // [T][B*H]
__device__ float  g_volt[BH];
__device__ float  g_asc[2 * BH];
__device__ float  g_fire[BH];

// ---------------- PTX helpers ------------------------------------------------
__device__ __forceinline__ void cp16(void* dst, const void* src) {
    uint32_t d = (uint32_t)__cvta_generic_to_shared(dst);
    asm volatile("cp.async.cg.shared.global [%0], [%1], 16;\n" :: "r"(d), "l"(src));
}
__device__ __forceinline__ void cp_commit() { asm volatile("cp.async.commit_group;\n"); }
__device__ __forceinline__ void cp_wait1()  { asm volatile("cp.async.wait_group 1;\n"); }

__device__ __forceinline__ void ldmx4(uint32_t* r, uint32_t addr) {
    asm volatile("ldmatrix.sync.aligned.m8n8.x4.shared.b16 {%0,%1,%2,%3}, [%4];\n"
                 : "=r"(r[0]), "=r"(r[1]), "=r"(r[2]), "=r"(r[3]) : "r"(addr));
}
__device__ __forceinline__ void ldmx4t(uint32_t* r, uint32_t addr) {
    asm volatile("ldmatrix.sync.aligned.m8n8.x4.trans.shared.b16 {%0,%1,%2,%3}, [%4];\n"
                 : "=r"(r[0]), "=r"(r[1]), "=r"(r[2]), "=r"(r[3]) : "r"(addr));
}
__device__ __forceinline__ void mma16816(float* c, const uint32_t* a, const uint32_t* b) {
    asm volatile(
        "mma.sync.aligned.m16n8k16.row.col.f32.f16.f16.f32 "
        "{%0,%1,%2,%3}, {%4,%5,%6,%7}, {%8,%9}, {%0,%1,%2,%3};\n"
        : "+f"(c[0]), "+f"(c[1]), "+f"(c[2]), "+f"(c[3])
        : "r"(a[0]), "r"(a[1]), "r"(a[2]), "r"(a[3]), "r"(b[0]), "r"(b[1]));
}

// ---------------- mma.sync GEMM: C[M,N] = A[M,K] @ B[K,N], fp32 accum --------
// BK = 64 halves (128B rows, SW128 xor swizzle, conflict-free ldmatrix)
// MODE 0: plain store   1: C += acc   2: bias + permuted store to [B][T][OUT]
template<int BM, int BN, int WM, int WN, int MODE>
__global__ __launch_bounds__(WM * WN * 32, MODE == 1 ? 4 : 2) void mgemm(
    const __half* __restrict__ A, const __half* __restrict__ Bm,
    float* __restrict__ C, const float* __restrict__ bias,
    int M, int N, int K)
{
    constexpr int THREADS = WM * WN * 32;
    constexpr int RPW = BM / WM;      // rows per warp
    constexpr int CPW = BN / WN;      // cols per warp
    constexpr int MF  = RPW / 16;     // m16 frags
    constexpr int NF  = CPW / 8;      // n8 frags (even)

    extern __shared__ __half smem[];
    __half* sA = smem;                    // [STG][BM*64]
    __half* sB = smem + STG * BM * 64;    // [STG][64*BN]

    const int tid  = threadIdx.x;
    const int l    = tid & 31;
    const int warp = tid >> 5;
    const int wm   = (warp / WN) * RPW;
    const int wn   = (warp % WN) * CPW;
    const int bm   = blockIdx.y * BM;
    const int bn   = blockIdx.x * BN;

    float acc[MF][NF][4] = {};

    const int KT = K >> 6;   // K / 64

    auto load_stage = [&](int kt, int st) {
        const int k0 = kt << 6;
        constexpr int GA = BM * 8 / THREADS;
#pragma unroll
        for (int i = 0; i < GA; i++) {
            int c = tid + i * THREADS;
            int row = c >> 3, g = c & 7;
            cp16(sA + st * BM * 64 + row * 64 + ((g ^ (row & 7)) << 3),
                 A + (size_t)(bm + row) * K + k0 + (g << 3));
        }
        constexpr int GB = 8 * BN / THREADS;
#pragma unroll
        for (int i = 0; i < GB; i++) {
            int c = tid + i * THREADS;
            int k = c / (BN / 8), g = c % (BN / 8);
            int blk = g >> 3, gg = (g & 7) ^ (k & 7);
            cp16(sB + st * 64 * BN + k * BN + blk * 64 + (gg << 3),
                 Bm + (size_t)(k0 + k) * N + bn + (g << 3));
        }
    };

    load_stage(0, 0); cp_commit();
    load_stage(1, 1); cp_commit();

    for (int kt = 0; kt < KT; kt++) {
        const int st = kt % STG;
        cp_wait1();
        __syncthreads();
        if (kt + 2 < KT) load_stage(kt + 2, (kt + 2) % STG);
        cp_commit();

        uint32_t baseA = (uint32_t)__cvta_generic_to_shared(sA + st * BM * 64);
        uint32_t baseB = (uint32_t)__cvta_generic_to_shared(sB + st * 64 * BN);

#pragma unroll
        for (int kk = 0; kk < 4; kk++) {
            uint32_t a[MF][4];
#pragma unroll
            for (int i = 0; i < MF; i++) {
                int row = wm + i * 16 + (l & 15);
                int g   = kk * 2 + (l >> 4);
                ldmx4(a[i], baseA + (uint32_t)(row * 64 + ((g ^ (row & 7)) << 3)) * 2);
            }
            uint32_t b[NF / 2][4];
#pragma unroll
            for (int j = 0; j < NF / 2; j++) {
                int k = kk * 16 + (l & 15);
                int g = ((wn + j * 16) >> 3) + (l >> 4);
                int blk = g >> 3, gg = (g & 7) ^ (k & 7);
                ldmx4t(b[j], baseB + (uint32_t)(k * BN + blk * 64 + (gg << 3)) * 2);
            }
#pragma unroll
            for (int i = 0; i < MF; i++)
#pragma unroll
                for (int j = 0; j < NF / 2; j++) {
                    mma16816(acc[i][2 * j],     a[i], b[j]);
                    mma16816(acc[i][2 * j + 1], a[i], b[j] + 2);
                }
        }
    }

    // ---- epilogue ----
    const int r  = l >> 2;
    const int c0 = (l & 3) * 2;
#pragma unroll
    for (int i = 0; i < MF; i++) {
        int m0 = bm + wm + i * 16;
#pragma unroll
        for (int j = 0; j < NF; j++) {
            int col = bn + wn + j * 8 + c0;
#pragma unroll
            for (int h = 0; h < 2; h++) {
                int m = m0 + r + h * 8;
                float2 val = make_float2(acc[i][j][2 * h], acc[i][j][2 * h + 1]);
                if (MODE == 0) {
                    *reinterpret_cast<float2*>(&C[(size_t)m * N + col]) = val;
                } else if (MODE == 1) {
                    float2* p = reinterpret_cast<float2*>(&C[(size_t)m * N + col]);
                    float2 o = *p;
                    o.x += val.x; o.y += val.y;
                    *p = o;
                } else {
                    float2 bb = *reinterpret_cast<const float2*>(&bias[col]);
                    val.x += bb.x; val.y += bb.y;
                    int t = m >> 6, b0 = m & 63;
                    *reinterpret_cast<float2*>(
                        &C[((size_t)b0 * TT + t) * OUTF + col]) = val;
                }
            }
        }
    }
}

// ---------------- conversion kernels -----------------------------------------
__global__ __launch_bounds__(256) void convx_kernel(const float* __restrict__ x,
                                                    __half* __restrict__ xh)
{
    int i  = blockIdx.x * 256 + threadIdx.x;          // over B*T*IN/4
    int i4 = i % (INF / 4);
    int bt = i / (INF / 4);
    int b = bt / TT, t = bt % TT;
    float4 v = reinterpret_cast<const float4*>(x)[i];
    int dst = (t * BB + b) * (INF / 4) + i4;
    reinterpret_cast<__half2*>(xh)[2 * dst + 0] = __floats2half2_rn(v.x, v.y);
    reinterpret_cast<__half2*>(xh)[2 * dst + 1] = __floats2half2_rn(v.z, v.w);
}

__global__ __launch_bounds__(256) void f2h_kernel(const float* __restrict__ in,
                                                  __half* __restrict__ out)
{
    int i = blockIdx.x * 256 + threadIdx.x;
    float4 v = reinterpret_cast<const float4*>(in)[i];
    reinterpret_cast<__half2*>(out)[2 * i + 0] = __floats2half2_rn(v.x, v.y);
    reinterpret_cast<__half2*>(out)[2 * i + 1] = __floats2half2_rn(v.z, v.w);
}

// W_out [OUT][HID] fp32 -> WoutT [HID][OUT] fp16
__global__ void transp_kernel(const float* __restrict__ w, __half* __restrict__ wt)
{
    __shared__ float tile[32][33];
    int ox = blockIdx.x * 32, hy = blockIdx.y * 32;
    int tx = threadIdx.x, ty = threadIdx.y;   // 32 x 8
#pragma unroll
    for (int rr = 0; rr < 32; rr += 8)
        tile[ty + rr][tx] = w[(size_t)(ox + ty + rr) * HID + hy + tx];
    __syncthreads();
#pragma unroll
    for (int rr = 0; rr < 32; rr += 8)
        wt[(size_t)(hy + ty + rr) * OUTF + ox + tx] = __float2half(tile[tx][ty + rr]);
}

// ---------------- elementwise 20-step scan -----------------------------------
__device__ __forceinline__ float sigm(float x) { return 1.0f / (1.0f + __expf(-x)); }

__global__ __launch_bounds__(256) void scan_kernel(
    const float* __restrict__ syn_all,
    const float* __restrict__ trans_k_m,
    const float* __restrict__ trans_asc_k,
    const float* __restrict__ asc_amp,
    const float* __restrict__ trans_asc_r,
    const float* __restrict__ thresh,
    __half* __restrict__ firing,
    float* __restrict__ volt_st, float* __restrict__ asc_st,
    float* __restrict__ fire_st, int t0)
{
    int idx = blockIdx.x * blockDim.x + threadIdx.x;
    int h = idx & (HID - 1);

    float syn[DELAYS];
#pragma unroll
    for (int s = 0; s < DELAYS; s++)
        syn[s] = syn_all[(size_t)(t0 + s) * BH + idx];

    float km  = sigm(trans_k_m[h]);
    float c1  = 0.1f * km;
    float c2  = 1.0f - km;
    float ka0 = sigm(trans_asc_k[h]);
    float ka1 = sigm(trans_asc_k[HID + h]);
    float amp0 = asc_amp[h],       amp1 = asc_amp[HID + h];
    float r0 = 1.0f - 2.0f * sigm(trans_asc_r[h]);
    float r1 = 1.0f - 2.0f * sigm(trans_asc_r[HID + h]);
    float th = thresh[h];

    float f, v, a0, a1;
    if (t0 == 0) {
        f = 0.f; v = 0.f; a0 = 0.f; a1 = 0.f;
    } else {
        f  = fire_st[idx];
        v  = volt_st[idx];
        a0 = asc_st[idx];
        a1 = asc_st[BH + idx];
    }

#pragma unroll
    for (int s = 0; s < DELAYS; s++) {
        a0 = (amp0 + r0 * a0) * f * ka0 + (1.0f - ka0) * a0;
        a1 = (amp1 + r1 * a1) * f * ka1 + (1.0f - ka1) * a1;
        v  = c1 * (syn[s] + a0 + a1) + c2 * v;
        f  = sigm(v - th);
        firing[(size_t)(t0 + s) * BH + idx] = __float2half(f);
    }
    fire_st[idx] = f;
    volt_st[idx] = v;
    asc_st[idx] = a0;
    asc_st[BH + idx] = a1;
}

// ---------------- launch ------------------------------------------------------
extern "C" void kernel_launch(void* const* d_in, const int* in_sizes, int n_in,
                              void* d_out, int out_size)
{
    const float* x           = (const float*)d_in[0];
    const float* W_in        = (const float*)d_in[1];
    const float* W_lat       = (const float*)d_in[2];
    const float* thresh      = (const float*)d_in[3];
    const float* trans_k_m   = (const float*)d_in[4];
    const float* trans_asc_k = (const float*)d_in[5];
    const float* asc_amp     = (const float*)d_in[6];
    const float* trans_asc_r = (const float*)d_in[7];
    const float* W_out       = (const float*)d_in[8];
    const float* b_out       = (const float*)d_in[9];
    float* out = (float*)d_out;

    __half *xh, *Win, *Wlat, *WoutT, *firing;
    float *syn, *volt, *asc, *fire;
    cudaGetSymbolAddress((void**)&xh,     g_xh);
    cudaGetSymbolAddress((void**)&Win,    g_Win);
    cudaGetSymbolAddress((void**)&Wlat,   g_Wlat);
    cudaGetSymbolAddress((void**)&WoutT,  g_WoutT);
    cudaGetSymbolAddress((void**)&syn,    g_syn);
    cudaGetSymbolAddress((void**)&firing, g_firing);
    cudaGetSymbolAddress((void**)&volt,   g_volt);
    cudaGetSymbolAddress((void**)&asc,    g_asc);
    cudaGetSymbolAddress((void**)&fire,   g_fire);

    // dynamic smem sizes
    const int SM_BIG = STG * (128 * 64 + 64 * 128) * 2;   // 98304
    const int SM_LAT = STG * (64 * 64 + 64 * 64) * 2;     // 49152
    cudaFuncSetAttribute(mgemm<128, 128, 4, 2, 0>,
                         cudaFuncAttributeMaxDynamicSharedMemorySize, SM_BIG);
    cudaFuncSetAttribute(mgemm<64, 64, 2, 2, 1>,
                         cudaFuncAttributeMaxDynamicSharedMemorySize, SM_LAT);
    cudaFuncSetAttribute(mgemm<128, 128, 4, 2, 2>,
                         cudaFuncAttributeMaxDynamicSharedMemorySize, SM_BIG);

    // 0. conversions
    convx_kernel<<<(BB * TT * INF / 4) / 256, 256>>>(x, xh);
    f2h_kernel<<<(INF * HID / 4) / 256, 256>>>(W_in, Win);
    f2h_kernel<<<(HID * HID / 4) / 256, 256>>>(W_lat, Wlat);
    transp_kernel<<<dim3(OUTF / 32, HID / 32), dim3(32, 8)>>>(W_out, WoutT);

    // 1. input projection: syn[t*64+b][h] = xh @ Win
    mgemm<128, 128, 4, 2, 0><<<dim3(HID / 128, (BB * TT) / 128), 256, SM_BIG>>>(
        xh, Win, syn, nullptr, BB * TT, HID, INF);

    // 2. ten blocks: lateral GEMM accumulates into syn slice, then scan
    for (int blk = 0; blk < NBLK; blk++) {
        if (blk > 0) {
            mgemm<64, 64, 2, 2, 1><<<dim3(HID / 64, (DELAYS * BB) / 64), 128, SM_LAT>>>(
                firing + (size_t)(blk - 1) * DELAYS * BH, Wlat,
                syn + (size_t)blk * DELAYS * BH, nullptr,
                DELAYS * BB, HID, HID);
        }
        scan_kernel<<<BH / 256, 256>>>(
            syn, trans_k_m, trans_asc_k, asc_amp, trans_asc_r, thresh,
            firing, volt, asc, fire, blk * DELAYS);
    }

    // 3. readout: out[b][t][o] = firing @ WoutT + bias (fused permute + bias)
    mgemm<128, 128, 4, 2, 2><<<dim3(OUTF / 128, (BB * TT) / 128), 256, SM_BIG>>>(
        firing, WoutT, out, b_out, BB * TT, OUTF, HID);
}